// round 1
// baseline (speedup 1.0000x reference)
#include <cuda_runtime.h>

// SphereConv: y[b,f,l,m] = relu/id( sqrt(1+l)/C * sum_c W[f,c,l] (*) x[b,c,l,m] )
// complex multiply, W linearly interpolated along l from N=64 knots.
// Strategy: fold scale/C into interpolated weights (linear op, scale>0 so relu
// commutes). One block per l; smem holds packed weights; packed f32x2 FMA
// (2x fp32 FMA throughput on sm_103a) keeps compute under the HBM roofline.

#define B_ 4
#define C_ 32
#define L_ 256
#define M_ 256
#define F_ 8
#define N_ 64

typedef unsigned long long u64;

__device__ __forceinline__ u64 pk2(float lo, float hi) {
    u64 r;
    asm("mov.b64 %0, {%1, %2};" : "=l"(r) : "f"(lo), "f"(hi));
    return r;
}
__device__ __forceinline__ void upk2(u64 v, float& lo, float& hi) {
    asm("mov.b64 {%0, %1}, %2;" : "=f"(lo), "=f"(hi) : "l"(v));
}
__device__ __forceinline__ u64 ffma2(u64 a, u64 b, u64 c) {
    u64 d;
    asm("fma.rn.f32x2 %0, %1, %2, %3;" : "=l"(d) : "l"(a), "l"(b), "l"(c));
    return d;
}

__global__ void __launch_bounds__(256, 2) sphere_conv_kernel(
    const float* __restrict__ xr, const float* __restrict__ xi,
    const float* __restrict__ wr, const float* __restrict__ wi,
    float* __restrict__ out)
{
    __shared__ float4 sw [C_ * F_];  // {s*wr, s*wr, s*wi, s*wi}
    __shared__ float2 swn[C_ * F_];  // {-s*wi, -s*wi}

    const int l   = blockIdx.x;
    const int tid = threadIdx.x;

    // --- per-block weight interpolation (one (f,c) per thread) ---
    {
        const int f = tid >> 5;        // 0..7
        const int c = tid & 31;        // 0..31
        float t = ((float)l / (float)(L_ - 1)) * (float)(N_ - 1);
        int lo = (int)floorf(t);
        lo = lo < 0 ? 0 : (lo > N_ - 2 ? N_ - 2 : lo);
        const float fr = t - (float)lo;
        const int base = (f * C_ + c) * N_ + lo;
        float wrv = wr[base] * (1.0f - fr) + wr[base + 1] * fr;
        float wiv = wi[base] * (1.0f - fr) + wi[base + 1] * fr;
        const float s = sqrtf(1.0f + (float)l) * (1.0f / (float)C_);
        wrv *= s; wiv *= s;
        sw [c * F_ + f] = make_float4(wrv, wrv, wiv, wiv);
        swn[c * F_ + f] = make_float2(-wiv, -wiv);
    }
    __syncthreads();

    const int b  = tid >> 6;          // 0..3
    const int mq = tid & 63;          // 0..63
    const int m0 = mq << 2;           // 4 m-values per thread

    const int base4 = (((b * C_) * L_ + l) * M_ + m0) >> 2;  // float4 index (c=0)
    const int cstr4 = (L_ * M_) >> 2;                        // float4 stride per c

    const float4* __restrict__ xr4 = (const float4*)xr;
    const float4* __restrict__ xi4 = (const float4*)xi;

    u64 aR[F_][2], aI[F_][2];
    #pragma unroll
    for (int f = 0; f < F_; ++f) {
        aR[f][0] = aR[f][1] = 0ull;
        aI[f][0] = aI[f][1] = 0ull;
    }

    #pragma unroll 4
    for (int c = 0; c < C_; ++c) {
        const float4 vr = __ldg(xr4 + base4 + c * cstr4);
        const float4 vi = __ldg(xi4 + base4 + c * cstr4);
        const u64 x_r0 = pk2(vr.x, vr.y), x_r1 = pk2(vr.z, vr.w);
        const u64 x_i0 = pk2(vi.x, vi.y), x_i1 = pk2(vi.z, vi.w);
        #pragma unroll
        for (int f = 0; f < F_; ++f) {
            const float4 w  = sw [c * F_ + f];
            const float2 wn = swn[c * F_ + f];
            const u64 wr2  = pk2(w.x,  w.y);   // +s*wr dup
            const u64 wi2  = pk2(w.z,  w.w);   // +s*wi dup
            const u64 nwi2 = pk2(wn.x, wn.y);  // -s*wi dup
            aR[f][0] = ffma2(wr2,  x_r0, aR[f][0]);
            aR[f][0] = ffma2(nwi2, x_i0, aR[f][0]);
            aR[f][1] = ffma2(wr2,  x_r1, aR[f][1]);
            aR[f][1] = ffma2(nwi2, x_i1, aR[f][1]);
            aI[f][0] = ffma2(wr2,  x_i0, aI[f][0]);
            aI[f][0] = ffma2(wi2,  x_r0, aI[f][0]);
            aI[f][1] = ffma2(wr2,  x_i1, aI[f][1]);
            aI[f][1] = ffma2(wi2,  x_r1, aI[f][1]);
        }
    }

    // --- epilogue: relu on real part only, write (2, B, F, L, M) ---
    const int outHalf = B_ * F_ * L_ * M_;
    #pragma unroll
    for (int f = 0; f < F_; ++f) {
        const int oR = ((b * F_ + f) * L_ + l) * M_ + m0;
        float r0, r1, r2, r3, i0, i1, i2, i3;
        upk2(aR[f][0], r0, r1); upk2(aR[f][1], r2, r3);
        upk2(aI[f][0], i0, i1); upk2(aI[f][1], i2, i3);
        const float4 yr = make_float4(fmaxf(r0, 0.0f), fmaxf(r1, 0.0f),
                                      fmaxf(r2, 0.0f), fmaxf(r3, 0.0f));
        const float4 yi = make_float4(i0, i1, i2, i3);
        *(float4*)(out + oR)           = yr;
        *(float4*)(out + outHalf + oR) = yi;
    }
}

extern "C" void kernel_launch(void* const* d_in, const int* in_sizes, int n_in,
                              void* d_out, int out_size) {
    const float* xr = (const float*)d_in[0];
    const float* xi = (const float*)d_in[1];
    const float* wr = (const float*)d_in[2];
    const float* wi = (const float*)d_in[3];
    float* out = (float*)d_out;
    sphere_conv_kernel<<<L_, 256>>>(xr, xi, wr, wi, out);
}